// round 14
// baseline (speedup 1.0000x reference)
#include <cuda_runtime.h>
#include <cuda_fp16.h>
#include <cstdint>

// LSTM scan: T=2048, B=4096, IN_S=1, H=20, OUT_S=1, no biases.
// Round 13: spread warps across SMSPs + fp32 u-term.
// Block = 128 threads = 4 INDEPENDENT warps (SMSPs 0-3), each warp owns 8
// batches with private SMEM slices and __syncwarp()-only stepping.
// Per warp-step: gates[8x80] = h_pad[8x20] x B via 10 tiles x
// (mma.m16n8k16 + mma.m16n8k8 for h16-19), fp16 in / fp32 accumulate;
// u*W_ih added in fp32 (fixes R12's fp16-u error). Column permutation puts
// each (batch,k)'s full (i,f,g,o) quad in one lane -> zero gate exchange.
// MUFU.TANH activations, sigmoid rows prescaled by 0.5. Grid 128 -> ~1
// block/SM, 1 warp/SMSP.

#define TSTEPS 2048
#define BATCH  4096
#define H      20
#define MB     8             // batches per warp
#define WPB    4             // warps per block
#define TPB    (32 * WPB)
#define CHUNK  64
#define NBLK   (BATCH / (MB * WPB))  // 128 blocks

__device__ __forceinline__ float tanha(float x) {
    float y;
    asm("tanh.approx.f32 %0, %1;" : "=f"(y) : "f"(x));
    return y;
}
__device__ __forceinline__ uint32_t pack_h2(float a, float b) {
    __half2 h = __floats2half2_rn(a, b);
    return *reinterpret_cast<uint32_t*>(&h);
}

__global__ void __launch_bounds__(TPB, 1)
lstm_mma_kernel(const float* __restrict__ u,     // [T, B, 1]
                const float* __restrict__ Wih,   // [80, 1]
                const float* __restrict__ Whh,   // [80, 20]
                const float* __restrict__ Wout,  // [1, 20]
                float* __restrict__ out)         // [T, B, 1]
{
    // Per-warp private slices. h: double-buffered, 16 rows x 40 halves
    // (80B stride -> conflict-free LDSM; rows 8-15 and cols >=20 stay zero).
    __shared__ __align__(16) __half h_sh[WPB][2][16][40];
    __shared__ float u_sh[WPB][CHUNK][MB];
    __shared__ float y_sh[WPB][CHUNK][MB];

    const int tid  = threadIdx.x;
    const int wid  = tid >> 5;
    const int lane = tid & 31;
    const int q    = lane & 3;    // column pair group; k offset
    const int nl   = lane >> 2;   // 0..7: batch row
    const int b0   = blockIdx.x * (MB * WPB) + wid * MB;

    // ---- Static fragments ----
    // Col n -> weight row: t=n/8, par=n&1, k=4*(t/2)+q,
    // gate = (t&1) ? 2+par : par (i,f,g,o), wrow = gate*20+k.
    // Sigmoid rows (gate != 2) prescaled by 0.5 (also applied to Wih term).
    uint32_t B0[10], B1[10], B2[10];
    float wih0[10], wih1[10];     // fp32 u-term weights for cols 8t+2q, +1
#pragma unroll
    for (int t = 0; t < 10; t++) {
        const int k = 4 * (t >> 1) + q;
        {   // B fragment col n = 8t + nl
            const int n = 8 * t + nl;
            const int gate = (t & 1) ? (2 + (n & 1)) : (n & 1);
            const int wrow = gate * H + 4 * (t >> 1) + ((n & 7) >> 1);
            const float s = (gate == 2) ? 1.0f : 0.5f;
            B0[t] = pack_h2(s * Whh[wrow * H + 2 * q],     s * Whh[wrow * H + 2 * q + 1]);
            B1[t] = pack_h2(s * Whh[wrow * H + 2 * q + 8], s * Whh[wrow * H + 2 * q + 9]);
            B2[t] = (q < 2) ? pack_h2(s * Whh[wrow * H + 16 + 2 * q],
                                      s * Whh[wrow * H + 17 + 2 * q]) : 0u;
        }
        {   // fp32 u-term weights for MY output cols n = 8t+2q (c0), +1 (c1)
            const int g0 = (t & 1) ? 2 : 0;   // even col -> i or g
            const int g1 = (t & 1) ? 3 : 1;   // odd col  -> f or o
            wih0[t] = ((g0 == 2) ? 1.0f : 0.5f) * Wih[g0 * H + k];
            wih1[t] = ((g1 == 2) ? 1.0f : 0.5f) * Wih[g1 * H + k];
        }
    }
    float wout[5];
#pragma unroll
    for (int m = 0; m < 5; m++) wout[m] = Wout[4 * m + q];

    // Zero all h buffers (rows 8-15 / pad cols stay zero forever).
    {
        uint32_t* hz = reinterpret_cast<uint32_t*>(&h_sh[0][0][0][0]);
        const int words = WPB * 2 * 16 * 40 / 2;
        for (int i = tid; i < words; i += TPB) hz[i] = 0u;
    }
    float cst[5] = {0.f, 0.f, 0.f, 0.f, 0.f};
    int pb = 0;
    __syncthreads();   // once, after zero-init

    const uint32_t h_base =
        (uint32_t)__cvta_generic_to_shared(&h_sh[wid][0][0][0]);
    const uint32_t BUFB = 16 * 40 * 2;   // 1280B per buffer
    // LDSM: lanes 0-15 -> rows 0-15 cols 0-7; lanes 16-31 -> +16B (cols 8-15).
    const uint32_t ldsm_off = (uint32_t)((lane & 15) * 80 + ((lane & 16) ? 16 : 0));
    // k8 A element: q<2 -> h row nl, cols 16+2q (byte 32+4q); q>=2 -> zero col 24.
    const uint32_t a2_off = (uint32_t)(nl * 80 + ((q < 2) ? (32 + 4 * q) : 48));

    __half* const hrow0 = &h_sh[wid][0][nl][0];
    __half* const hrow1 = &h_sh[wid][1][nl][0];
    const float zc = 0.0f;

#pragma unroll 1
    for (int tc = 0; tc < TSTEPS / CHUNK; tc++) {
        // Flush y of previous chunk (per-warp slice).
        if (tc > 0) {
            const int t0p = (tc - 1) * CHUNK;
#pragma unroll 1
            for (int e = lane; e < CHUNK * MB; e += 32) {
                const int rr = e >> 3, row = e & 7;
                out[(t0p + rr) * BATCH + b0 + row] = y_sh[wid][rr][row];
            }
        }
        // Stage u (fp32) for this chunk.
        {
            const float* uc = u + tc * CHUNK * BATCH + b0;
#pragma unroll 1
            for (int e = lane; e < CHUNK * MB; e += 32) {
                const int rr = e >> 3, row = e & 7;
                u_sh[wid][rr][row] = uc[rr * BATCH + row];
            }
        }
        __syncwarp();

#pragma unroll 1
        for (int tt = 0; tt < CHUNK; tt++) {
            const uint32_t buf = h_base + (uint32_t)pb * BUFB;

            uint32_t A0, A1, A2, A3;
            asm volatile("ldmatrix.sync.aligned.m8n8.x4.shared.b16 {%0,%1,%2,%3}, [%4];\n"
                         : "=r"(A0), "=r"(A1), "=r"(A2), "=r"(A3)
                         : "r"(buf + ldsm_off));
            uint32_t Aa;
            asm volatile("ld.shared.b32 %0, [%1];\n" : "=r"(Aa) : "r"(buf + a2_off));
            const uint32_t Ab = 0u;   // rows 8-15 of k8 chunk: zero

            const float x = u_sh[wid][tt][nl];

            float d[10][4];
#pragma unroll
            for (int t = 0; t < 10; t++) {
                asm volatile(
                    "mma.sync.aligned.m16n8k16.row.col.f32.f16.f16.f32 "
                    "{%0,%1,%2,%3}, {%4,%5,%6,%7}, {%8,%9}, {%10,%11,%12,%13};\n"
                    : "=f"(d[t][0]), "=f"(d[t][1]), "=f"(d[t][2]), "=f"(d[t][3])
                    : "r"(A0), "r"(A1), "r"(A2), "r"(A3),
                      "r"(B0[t]), "r"(B1[t]),
                      "f"(zc), "f"(zc), "f"(zc), "f"(zc));
                asm volatile(
                    "mma.sync.aligned.m16n8k8.row.col.f32.f16.f16.f32 "
                    "{%0,%1,%2,%3}, {%4,%5}, {%6}, {%0,%1,%2,%3};\n"
                    : "+f"(d[t][0]), "+f"(d[t][1]), "+f"(d[t][2]), "+f"(d[t][3])
                    : "r"(Aa), "r"(Ab), "r"(B2[t]));
            }

            // Activations + state update; u-term added in fp32.
            // Tile 2m: (i,f) of k=4m+q; tile 2m+1: (g,o). All in-lane.
            __half* const hrow = pb ? hrow0 : hrow1;   // write the OTHER buffer
            float yp = 0.0f;
#pragma unroll
            for (int m = 0; m < 5; m++) {
                const float ai = fmaf(x, wih0[2 * m],     d[2 * m][0]);
                const float af = fmaf(x, wih1[2 * m],     d[2 * m][1]);
                const float ag = fmaf(x, wih0[2 * m + 1], d[2 * m + 1][0]);
                const float ao = fmaf(x, wih1[2 * m + 1], d[2 * m + 1][1]);
                const float zi = fmaf(0.5f, tanha(ai), 0.5f);
                const float zf = fmaf(0.5f, tanha(af), 0.5f);
                const float zg = tanha(ag);
                const float zo = fmaf(0.5f, tanha(ao), 0.5f);
                cst[m] = fmaf(zf, cst[m], zi * zg);
                const float h = zo * tanha(cst[m]);
                yp = fmaf(h, wout[m], yp);
                hrow[4 * m + q] = __float2half_rn(h);
            }

            // y reduce over the 4 lanes (q group) of my batch row.
            yp += __shfl_xor_sync(0xffffffffu, yp, 1);
            yp += __shfl_xor_sync(0xffffffffu, yp, 2);
            if (q == 0) y_sh[wid][tt][nl] = yp;

            __syncwarp();     // h_t visible to the whole warp for next LDSM
            pb ^= 1;
        }
    }

    // Final chunk flush.
    {
        const int t0p = (TSTEPS / CHUNK - 1) * CHUNK;
#pragma unroll 1
        for (int e = lane; e < CHUNK * MB; e += 32) {
            const int rr = e >> 3, row = e & 7;
            out[(t0p + rr) * BATCH + b0 + row] = y_sh[wid][rr][row];
        }
    }
}

extern "C" void kernel_launch(void* const* d_in, const int* in_sizes, int n_in,
                              void* d_out, int out_size) {
    const float* u    = (const float*)d_in[0];  // [2048, 4096, 1]
    const float* Wih  = (const float*)d_in[1];  // [80, 1]
    const float* Whh  = (const float*)d_in[2];  // [80, 20]
    const float* Wout = (const float*)d_in[3];  // [1, 20]
    float* out = (float*)d_out;                 // [2048, 4096, 1]

    lstm_mma_kernel<<<NBLK, TPB>>>(u, Wih, Whh, Wout, out);
}